// round 5
// baseline (speedup 1.0000x reference)
#include <cuda_runtime.h>
#include <cuda_bf16.h>
#include <cstdint>
#include <math.h>

// Problem constants
#define BATCH 2
#define SEQ   2048
#define DMODEL 1024
#define NHEADS 16
#define DK    64
#define MROWS (BATCH * SEQ)     // 4096
#define ATT_SCALE 0.125f        // 1/sqrt(64)

// ---------------- scratch (device globals; no cudaMalloc allowed) ----------
__device__ float g_Q[MROWS * DMODEL];
__device__ float g_K[MROWS * DMODEL];
__device__ float g_V[MROWS * DMODEL];
__device__ float g_O[MROWS * DMODEL];

// ---------------- helpers ---------------------------------------------------
__device__ __forceinline__ uint32_t f2tf(float f) {
    uint32_t u;
    asm("cvt.rna.tf32.f32 %0, %1;" : "=r"(u) : "f"(f));
    return u;
}

__device__ __forceinline__ void mma_tf32(float c[4],
                                         uint32_t a0, uint32_t a1, uint32_t a2, uint32_t a3,
                                         uint32_t b0, uint32_t b1) {
    asm volatile(
        "mma.sync.aligned.m16n8k8.row.col.f32.tf32.tf32.f32 "
        "{%0,%1,%2,%3}, {%4,%5,%6,%7}, {%8,%9}, {%0,%1,%2,%3};"
        : "+f"(c[0]), "+f"(c[1]), "+f"(c[2]), "+f"(c[3])
        : "r"(a0), "r"(a1), "r"(a2), "r"(a3), "r"(b0), "r"(b1));
}

// ---------------- GEMM: C[M,N] = A[M,K] * B[N,K]^T  (tf32 tensor core) -----
// Block 128 threads (4 warps, 2x2), block tile 128x128, warp tile 64x64,
// k-chunk 32.
#define GMT 128
#define GNT 128
#define GKT 32
#define GSTR 36

__global__ __launch_bounds__(128, 2) void gemm_nt_tc(const float* __restrict__ A,
                                                     const float* __restrict__ Bm,
                                                     float* __restrict__ C,
                                                     int M, int N, int K) {
    __shared__ uint32_t As[GMT * GSTR];
    __shared__ uint32_t Bs[GNT * GSTR];

    const int tid  = threadIdx.x;
    const int lane = tid & 31;
    const int warp = tid >> 5;
    const int g  = lane >> 2;      // 0..7
    const int tq = lane & 3;       // 0..3
    const int wm = (warp & 1) * 64;
    const int wn = (warp >> 1) * 64;
    const int rowBase = blockIdx.y * GMT;
    const int colBase = blockIdx.x * GNT;

    float acc[4][8][4];
#pragma unroll
    for (int i = 0; i < 4; i++)
#pragma unroll
        for (int j = 0; j < 8; j++)
#pragma unroll
            for (int t = 0; t < 4; t++) acc[i][j][t] = 0.f;

    const float* Ap = A  + (size_t)(rowBase + tid) * K;
    const float* Bp = Bm + (size_t)(colBase + tid) * K;

    for (int k0 = 0; k0 < K; k0 += GKT) {
#pragma unroll
        for (int u = 0; u < 8; u++) {
            float4 va = *reinterpret_cast<const float4*>(Ap + k0 + u * 4);
            uint32_t* d = &As[tid * GSTR + u * 4];
            d[0] = f2tf(va.x); d[1] = f2tf(va.y); d[2] = f2tf(va.z); d[3] = f2tf(va.w);
            float4 vb = *reinterpret_cast<const float4*>(Bp + k0 + u * 4);
            uint32_t* e = &Bs[tid * GSTR + u * 4];
            e[0] = f2tf(vb.x); e[1] = f2tf(vb.y); e[2] = f2tf(vb.z); e[3] = f2tf(vb.w);
        }
        __syncthreads();

#pragma unroll
        for (int ks = 0; ks < 4; ks++) {
            const int kk = ks * 8;
            uint32_t a[4][4], b[8][2];
#pragma unroll
            for (int i = 0; i < 4; i++) {
                a[i][0] = As[(wm + 16 * i + g) * GSTR + kk + tq];
                a[i][1] = As[(wm + 16 * i + g + 8) * GSTR + kk + tq];
                a[i][2] = As[(wm + 16 * i + g) * GSTR + kk + tq + 4];
                a[i][3] = As[(wm + 16 * i + g + 8) * GSTR + kk + tq + 4];
            }
#pragma unroll
            for (int j = 0; j < 8; j++) {
                b[j][0] = Bs[(wn + 8 * j + g) * GSTR + kk + tq];
                b[j][1] = Bs[(wn + 8 * j + g) * GSTR + kk + tq + 4];
            }
#pragma unroll
            for (int i = 0; i < 4; i++)
#pragma unroll
                for (int j = 0; j < 8; j++)
                    mma_tf32(acc[i][j], a[i][0], a[i][1], a[i][2], a[i][3],
                             b[j][0], b[j][1]);
        }
        __syncthreads();
    }

#pragma unroll
    for (int i = 0; i < 4; i++) {
        const int r0 = rowBase + wm + 16 * i + g;
#pragma unroll
        for (int j = 0; j < 8; j++) {
            const int c0 = colBase + wn + 8 * j + 2 * tq;
            *reinterpret_cast<float2*>(&C[(size_t)r0 * N + c0]) =
                make_float2(acc[i][j][0], acc[i][j][1]);
            *reinterpret_cast<float2*>(&C[(size_t)(r0 + 8) * N + c0]) =
                make_float2(acc[i][j][2], acc[i][j][3]);
        }
    }
}

// ---------------- Flash attention (tf32 tensor core, P in registers) --------
// Block 128 threads (4 warps), 128-query tile, 64-key tiles.
// Warp w owns query rows 32w..32w+31 (two m16 fragment rows).
// PV trick: k-permutation sigma(s) = (s<4 ? 2s : 2s-7) makes the S C-fragment
// exactly the PV A-fragment; V B-fragments use rows 8jk+2tq, 8jk+2tq+1.
#define QT 128
#define KT 64
#define QSTR 68
#define KSTR 68
#define VSTR 68
#define OFF_Q 0
#define OFF_K (QT * QSTR)               // 8704
#define OFF_V (OFF_K + KT * KSTR)       // 13056
#define FLASH_WORDS (OFF_V + KT * VSTR) // 17408
#define FLASH_SMEM (FLASH_WORDS * 4)    // 69632 B

__global__ __launch_bounds__(128, 2) void flash_tc(const float* __restrict__ Q,
                                                   const float* __restrict__ K,
                                                   const float* __restrict__ V,
                                                   float* __restrict__ O) {
    extern __shared__ uint32_t sm[];
    uint32_t* Qs = sm + OFF_Q;
    uint32_t* Ks = sm + OFF_K;
    uint32_t* Vs = sm + OFF_V;

    const int tid  = threadIdx.x;
    const int lane = tid & 31;
    const int warp = tid >> 5;
    const int g  = lane >> 2;
    const int tq = lane & 3;
    const int r0 = warp * 32;

    const int bh = blockIdx.y;
    const int b  = bh / NHEADS;
    const int h  = bh % NHEADS;
    const int qBase = blockIdx.x * QT;

    // Load Q tile (128 x 64): one full row per thread
    {
        const float* qp = Q + (size_t)(b * SEQ + qBase + tid) * DMODEL + h * DK;
#pragma unroll
        for (int u = 0; u < 16; u++) {
            float4 v = *reinterpret_cast<const float4*>(qp + u * 4);
            uint32_t* d = &Qs[tid * QSTR + u * 4];
            d[0] = f2tf(v.x); d[1] = f2tf(v.y); d[2] = f2tf(v.z); d[3] = f2tf(v.w);
        }
    }

    float m[2][2], l[2][2], o[2][8][4];
#pragma unroll
    for (int r = 0; r < 2; r++) {
        m[r][0] = -INFINITY; m[r][1] = -INFINITY;
        l[r][0] = 0.f;       l[r][1] = 0.f;
#pragma unroll
        for (int j = 0; j < 8; j++)
#pragma unroll
            for (int t = 0; t < 4; t++) o[r][j][t] = 0.f;
    }

    for (int kt = 0; kt < SEQ / KT; kt++) {
        __syncthreads();  // prev iter's Ks/Vs fully consumed
        {
            const int lr = tid >> 1;
            const int lc = (tid & 1) * 32;
            const float* kp = K + (size_t)(b * SEQ + kt * KT + lr) * DMODEL + h * DK + lc;
            const float* vp = V + (size_t)(b * SEQ + kt * KT + lr) * DMODEL + h * DK + lc;
#pragma unroll
            for (int u = 0; u < 8; u++) {
                float4 v = *reinterpret_cast<const float4*>(kp + u * 4);
                uint32_t* d = &Ks[lr * KSTR + lc + u * 4];
                d[0] = f2tf(v.x); d[1] = f2tf(v.y); d[2] = f2tf(v.z); d[3] = f2tf(v.w);
                float4 w = *reinterpret_cast<const float4*>(vp + u * 4);
                uint32_t* e = &Vs[lr * VSTR + lc + u * 4];
                e[0] = f2tf(w.x); e[1] = f2tf(w.y); e[2] = f2tf(w.z); e[3] = f2tf(w.w);
            }
        }
        __syncthreads();

        // S = Q K^T  (32 x 64 per warp)
        float s[2][8][4];
#pragma unroll
        for (int r = 0; r < 2; r++)
#pragma unroll
            for (int j = 0; j < 8; j++)
#pragma unroll
                for (int t = 0; t < 4; t++) s[r][j][t] = 0.f;

#pragma unroll
        for (int ks = 0; ks < 8; ks++) {
            const int kk = ks * 8;
            uint32_t a[2][4];
#pragma unroll
            for (int r = 0; r < 2; r++) {
                const int rr = r0 + 16 * r;
                a[r][0] = Qs[(rr + g) * QSTR + kk + tq];
                a[r][1] = Qs[(rr + g + 8) * QSTR + kk + tq];
                a[r][2] = Qs[(rr + g) * QSTR + kk + tq + 4];
                a[r][3] = Qs[(rr + g + 8) * QSTR + kk + tq + 4];
            }
#pragma unroll
            for (int j = 0; j < 8; j++) {
                uint32_t b0 = Ks[(8 * j + g) * KSTR + kk + tq];
                uint32_t b1 = Ks[(8 * j + g) * KSTR + kk + tq + 4];
                mma_tf32(s[0][j], a[0][0], a[0][1], a[0][2], a[0][3], b0, b1);
                mma_tf32(s[1][j], a[1][0], a[1][1], a[1][2], a[1][3], b0, b1);
            }
        }

        // Online softmax per row-block (c0,c1 -> row g; c2,c3 -> row g+8)
#pragma unroll
        for (int r = 0; r < 2; r++) {
            float rm0 = -INFINITY, rm1 = -INFINITY;
#pragma unroll
            for (int j = 0; j < 8; j++) {
                s[r][j][0] *= ATT_SCALE; s[r][j][1] *= ATT_SCALE;
                s[r][j][2] *= ATT_SCALE; s[r][j][3] *= ATT_SCALE;
                rm0 = fmaxf(rm0, fmaxf(s[r][j][0], s[r][j][1]));
                rm1 = fmaxf(rm1, fmaxf(s[r][j][2], s[r][j][3]));
            }
            rm0 = fmaxf(rm0, __shfl_xor_sync(0xffffffffu, rm0, 1));
            rm0 = fmaxf(rm0, __shfl_xor_sync(0xffffffffu, rm0, 2));
            rm1 = fmaxf(rm1, __shfl_xor_sync(0xffffffffu, rm1, 1));
            rm1 = fmaxf(rm1, __shfl_xor_sync(0xffffffffu, rm1, 2));

            const float mn0 = fmaxf(m[r][0], rm0);
            const float mn1 = fmaxf(m[r][1], rm1);
            const float al0 = __expf(m[r][0] - mn0);
            const float al1 = __expf(m[r][1] - mn1);
            m[r][0] = mn0; m[r][1] = mn1;

            float rs0 = 0.f, rs1 = 0.f;
#pragma unroll
            for (int j = 0; j < 8; j++) {
                float p0 = __uint_as_float(f2tf(__expf(s[r][j][0] - mn0)));
                float p1 = __uint_as_float(f2tf(__expf(s[r][j][1] - mn0)));
                float p2 = __uint_as_float(f2tf(__expf(s[r][j][2] - mn1)));
                float p3 = __uint_as_float(f2tf(__expf(s[r][j][3] - mn1)));
                rs0 += p0 + p1; rs1 += p2 + p3;
                s[r][j][0] = p0; s[r][j][1] = p1;
                s[r][j][2] = p2; s[r][j][3] = p3;
            }
            rs0 += __shfl_xor_sync(0xffffffffu, rs0, 1);
            rs0 += __shfl_xor_sync(0xffffffffu, rs0, 2);
            rs1 += __shfl_xor_sync(0xffffffffu, rs1, 1);
            rs1 += __shfl_xor_sync(0xffffffffu, rs1, 2);
            l[r][0] = l[r][0] * al0 + rs0;
            l[r][1] = l[r][1] * al1 + rs1;

#pragma unroll
            for (int j = 0; j < 8; j++) {
                o[r][j][0] *= al0; o[r][j][1] *= al0;
                o[r][j][2] *= al1; o[r][j][3] *= al1;
            }
        }

        // O += P V with permuted k-order: C-frag of S is directly the A-frag.
        // A slot (k=tq)   <- key 2tq   -> a0=c0, a1=c2
        // A slot (k=tq+4) <- key 2tq+1 -> a2=c1, a3=c3
        // B rows: 8jk+2tq and 8jk+2tq+1.
#pragma unroll
        for (int jk = 0; jk < 8; jk++) {
            const int kr = 8 * jk + 2 * tq;
#pragma unroll
            for (int jd = 0; jd < 8; jd++) {
                uint32_t b0 = Vs[kr * VSTR + 8 * jd + g];
                uint32_t b1 = Vs[(kr + 1) * VSTR + 8 * jd + g];
#pragma unroll
                for (int r = 0; r < 2; r++) {
                    mma_tf32(o[r][jd],
                             __float_as_uint(s[r][jk][0]),
                             __float_as_uint(s[r][jk][2]),
                             __float_as_uint(s[r][jk][1]),
                             __float_as_uint(s[r][jk][3]),
                             b0, b1);
                }
            }
        }
    }

    // Epilogue: normalize and store (undo head split)
#pragma unroll
    for (int r = 0; r < 2; r++) {
        const float inv0 = 1.f / l[r][0];
        const float inv1 = 1.f / l[r][1];
        const size_t row0 = (size_t)(b * SEQ + qBase + r0 + 16 * r + g);
#pragma unroll
        for (int jd = 0; jd < 8; jd++) {
            const int c = h * DK + 8 * jd + 2 * tq;
            *reinterpret_cast<float2*>(&O[row0 * DMODEL + c]) =
                make_float2(o[r][jd][0] * inv0, o[r][jd][1] * inv0);
            *reinterpret_cast<float2*>(&O[(row0 + 8) * DMODEL + c]) =
                make_float2(o[r][jd][2] * inv1, o[r][jd][3] * inv1);
        }
    }
}

// ---------------- launch ---------------------------------------------------
extern "C" void kernel_launch(void* const* d_in, const int* in_sizes, int n_in,
                              void* d_out, int out_size) {
    const float* x  = (const float*)d_in[0];
    const float* Wq = (const float*)d_in[1];
    const float* Wk = (const float*)d_in[2];
    const float* Wv = (const float*)d_in[3];
    const float* Wo = (const float*)d_in[4];
    float* out = (float*)d_out;

    float *Qp, *Kp, *Vp, *Op;
    cudaGetSymbolAddress((void**)&Qp, g_Q);
    cudaGetSymbolAddress((void**)&Kp, g_K);
    cudaGetSymbolAddress((void**)&Vp, g_V);
    cudaGetSymbolAddress((void**)&Op, g_O);

    cudaFuncSetAttribute(flash_tc, cudaFuncAttributeMaxDynamicSharedMemorySize,
                         FLASH_SMEM);

    dim3 gGemm(DMODEL / GNT, MROWS / GMT);  // (8, 32)
    gemm_nt_tc<<<gGemm, 128>>>(x, Wq, Qp, MROWS, DMODEL, DMODEL);
    gemm_nt_tc<<<gGemm, 128>>>(x, Wk, Kp, MROWS, DMODEL, DMODEL);
    gemm_nt_tc<<<gGemm, 128>>>(x, Wv, Vp, MROWS, DMODEL, DMODEL);

    dim3 gFlash(SEQ / QT, BATCH * NHEADS);  // (16, 32)
    flash_tc<<<gFlash, 128, FLASH_SMEM>>>(Qp, Kp, Vp, Op);

    gemm_nt_tc<<<gGemm, 128>>>(Op, Wo, out, MROWS, DMODEL, DMODEL);
}